// round 8
// baseline (speedup 1.0000x reference)
#include <cuda_runtime.h>
#include <cuda_fp16.h>
#include <cstdint>

#define Hh 192
#define Ww 192
#define HWsz (192*192)
#define Cc 32
#define Tt 8
#define KK 9

// Channels-last fp16 scratch: [B][T][HW][C]  (37.7 MB)
__device__ __half g_scratch_h[(size_t)2 * Tt * HWsz * Cc];
// fp16 weights in m16n8k16 fragment order: [t][tap][ks(2)][nt(4)][lane(32)][2 x u32(half2)]
__device__ uint32_t g_wfrag[(size_t)Tt * KK * 2 * 4 * 32 * 2];

__device__ __forceinline__ void mma_f16(float* c, uint32_t a0, uint32_t a1,
                                        uint32_t a2, uint32_t a3,
                                        uint32_t b0, uint32_t b1) {
    asm volatile(
        "mma.sync.aligned.m16n8k16.row.col.f32.f16.f16.f32 "
        "{%0,%1,%2,%3}, {%4,%5,%6,%7}, {%8,%9}, {%0,%1,%2,%3};"
        : "+f"(c[0]), "+f"(c[1]), "+f"(c[2]), "+f"(c[3])
        : "r"(a0), "r"(a1), "r"(a2), "r"(a3), "r"(b0), "r"(b1));
}

// ---------- Kernel 1: transpose (+ weight prep in extra blocks) ----------
// grid = (1153, 16): x<1152 -> transpose tile; x==1152 -> wprep for t=by>>1, half=by&1
__global__ __launch_bounds__(256) void prep_k(const float* __restrict__ feat,
                                              const float* __restrict__ weight) {
    if (blockIdx.x == 1152) {
        const int t = blockIdx.y >> 1;
        const int half = blockIdx.y & 1;
        for (int it = half * 9; it < half * 9 + 9; it++) {
            const int j = it * 256 + threadIdx.x;    // j < 4608
            const int reg  = j & 1;
            const int lane = (j >> 1) & 31;
            const int nt   = (j >> 6) & 3;
            const int ks   = (j >> 8) & 1;
            const int tap  = j >> 9;                 // 0..8
            const int r0 = lane >> 2, c0 = lane & 3;
            const int cout = nt * 8 + r0;
            const int cin0 = ks * 16 + 2 * c0 + reg * 8;
            const float w0 = weight[((size_t)(t * Cc + cout) * Cc + cin0) * KK + tap];
            const float w1 = weight[((size_t)(t * Cc + cout) * Cc + cin0 + 1) * KK + tap];
            const __half2 h = __floats2half2_rn(w0, w1);
            g_wfrag[(size_t)t * 4608 + j] = *(const uint32_t*)&h;
        }
        return;
    }
    __shared__ float tl[32][33];
    const int bt = blockIdx.y;
    const int b = bt >> 3, t = bt & 7;
    const int hw0 = blockIdx.x * 32;
    const int x = threadIdx.x & 31;
    const int y = threadIdx.x >> 5;
    #pragma unroll
    for (int j = 0; j < 4; j++) {
        const int c = y + j * 8;
        tl[c][x] = feat[((size_t)(b * Cc + c) * Tt + t) * HWsz + hw0 + x];
    }
    __syncthreads();
    uint32_t* gdst = (uint32_t*)g_scratch_h + ((size_t)bt * HWsz + hw0) * 16;
    #pragma unroll
    for (int it = 0; it < 2; it++) {
        const int idx = it * 256 + threadIdx.x;   // 0..511
        const int hwl = idx >> 4;
        const int cp  = idx & 15;                 // channel pair
        const __half2 h = __floats2half2_rn(tl[2 * cp][hwl], tl[2 * cp + 1][hwl]);
        gdst[hwl * 16 + cp] = *(const uint32_t*)&h;
    }
}

// ---------- Kernel 2: fused deform-sample + mma.sync f16 GEMM ----------
// smem: A slabs 8 warps x 32 pix x 20 u32 = 20480B; epilogue D 32x260 f32 = 33280B
#define SM_TOTAL 33280
#define APAD2 20
#define DPAD 260

__global__ __launch_bounds__(256, 3) void dcn_main(
    const float* __restrict__ offset,   // [B, 18, T, H, W]
    float* __restrict__ out)            // [B, 32, T, H, W]
{
    extern __shared__ char smem[];
    const int tid  = threadIdx.x;
    const int wid  = tid >> 5;
    const int lane = tid & 31;
    const int bt = blockIdx.y;
    const int b = bt >> 3, t = bt & 7;
    const int pix0  = blockIdx.x * 256;
    const int pixw0 = pix0 + wid * 32;

    uint32_t* sa = (uint32_t*)smem + wid * (32 * APAD2);  // warp-private fp16 A slab
    const uint2* sbase = (const uint2*)g_scratch_h + (size_t)bt * HWsz * 8 + (lane & 7);
    const float* offb = offset + ((size_t)b * 2 * KK * Tt + t) * HWsz + pixw0;
    const uint32_t* gwf = g_wfrag + (size_t)t * 4608 + lane * 2;

    float acc[2][4][4];
    #pragma unroll
    for (int s = 0; s < 2; s++)
        #pragma unroll
        for (int n = 0; n < 4; n++)
            #pragma unroll
            for (int r = 0; r < 4; r++) acc[s][n][r] = 0.f;

    const size_t ostr = (size_t)Tt * HWsz;
    float odyv = offb[lane];
    float odxv = offb[ostr + lane];

    #pragma unroll 1
    for (int k = 0; k < KK; k++) {
        // Prefetch next tap's offsets (hidden behind this tap's work).
        float ndy = 0.f, ndx = 0.f;
        if (k < KK - 1) {
            ndy = offb[(size_t)(2 * k + 2) * ostr / (Tt * HWsz) * ostr + 0];  // placeholder avoided below
        }
        // (issue real prefetch loads)
        if (k < KK - 1) {
            ndy = offb[(size_t)(2 * k + 2) * ostr + lane];
            ndx = offb[(size_t)(2 * k + 3) * ostr + lane];
        }
        const int dky = k / 3 - 1;
        const int dkx = k - (k / 3) * 3 - 1;

        #pragma unroll 2
        for (int p = 0; p < 8; p++) {
            const int pixl = p * 4 + (lane >> 3);
            const int pixg = pixw0 + pixl;
            const int h = (int)((unsigned)pixg / Ww);
            const int w = pixg - h * Ww;

            const float dy = __shfl_sync(0xffffffffu, odyv, pixl);
            const float dx = __shfl_sync(0xffffffffu, odxv, pixl);
            const float ys = dy + (float)(h + dky);
            const float xs = dx + (float)(w + dkx);

            const float y0f = floorf(ys), x0f = floorf(xs);
            const int iy0 = (int)y0f, ix0 = (int)x0f;
            const int iy1 = iy0 + 1,  ix1 = ix0 + 1;
            const float fy = ys - y0f, fx = xs - x0f;
            const float gy = 1.f - fy, gx = 1.f - fx;

            const bool vy0 = (unsigned)iy0 < Hh;
            const bool vy1 = (unsigned)iy1 < Hh;
            const bool vx0 = (unsigned)ix0 < Ww;
            const bool vx1 = (unsigned)ix1 < Ww;
            const int cy0 = min(max(iy0, 0), Hh - 1);
            const int cy1 = min(max(iy1, 0), Hh - 1);
            const int cx0 = min(max(ix0, 0), Ww - 1);
            const int cx1 = min(max(ix1, 0), Ww - 1);

            const float w00 = (vy0 && vx0) ? gy * gx : 0.f;
            const float w01 = (vy0 && vx1) ? gy * fx : 0.f;
            const float w10 = (vy1 && vx0) ? fy * gx : 0.f;
            const float w11 = (vy1 && vx1) ? fy * fx : 0.f;

            const uint2 q00 = sbase[(size_t)(cy0 * Ww + cx0) * 8];
            const uint2 q01 = sbase[(size_t)(cy0 * Ww + cx1) * 8];
            const uint2 q10 = sbase[(size_t)(cy1 * Ww + cx0) * 8];
            const uint2 q11 = sbase[(size_t)(cy1 * Ww + cx1) * 8];

            const float2 a00l = __half22float2(*(const __half2*)&q00.x);
            const float2 a00h = __half22float2(*(const __half2*)&q00.y);
            const float2 a01l = __half22float2(*(const __half2*)&q01.x);
            const float2 a01h = __half22float2(*(const __half2*)&q01.y);
            const float2 a10l = __half22float2(*(const __half2*)&q10.x);
            const float2 a10h = __half22float2(*(const __half2*)&q10.y);
            const float2 a11l = __half22float2(*(const __half2*)&q11.x);
            const float2 a11h = __half22float2(*(const __half2*)&q11.y);

            const float v0 = fmaf(w00, a00l.x, fmaf(w01, a01l.x, fmaf(w10, a10l.x, w11 * a11l.x)));
            const float v1 = fmaf(w00, a00l.y, fmaf(w01, a01l.y, fmaf(w10, a10l.y, w11 * a11l.y)));
            const float v2 = fmaf(w00, a00h.x, fmaf(w01, a01h.x, fmaf(w10, a10h.x, w11 * a11h.x)));
            const float v3 = fmaf(w00, a00h.y, fmaf(w01, a01h.y, fmaf(w10, a10h.y, w11 * a11h.y)));

            const __half2 h01 = __floats2half2_rn(v0, v1);
            const __half2 h23 = __floats2half2_rn(v2, v3);
            uint2 u; u.x = *(const uint32_t*)&h01; u.y = *(const uint32_t*)&h23;
            *(uint2*)(sa + pixl * APAD2 + (lane & 7) * 2) = u;
        }
        __syncwarp();

        // ---- MMA: D[32pix x 32cout] += A(fp16) * W_k^T(fp16), 2 K-steps of 16 ----
        const int r0 = lane >> 2;
        const int c0 = lane & 3;
        #pragma unroll
        for (int ks = 0; ks < 2; ks++) {
            const int cb = ks * 8 + c0;
            const uint32_t a00_ = sa[r0 * APAD2 + cb];
            const uint32_t a01_ = sa[(r0 + 8) * APAD2 + cb];
            const uint32_t a02_ = sa[r0 * APAD2 + cb + 4];
            const uint32_t a03_ = sa[(r0 + 8) * APAD2 + cb + 4];
            const uint32_t a10_ = sa[(r0 + 16) * APAD2 + cb];
            const uint32_t a11_ = sa[(r0 + 24) * APAD2 + cb];
            const uint32_t a12_ = sa[(r0 + 16) * APAD2 + cb + 4];
            const uint32_t a13_ = sa[(r0 + 24) * APAD2 + cb + 4];
            #pragma unroll
            for (int nt = 0; nt < 4; nt++) {
                const uint2 bb = __ldg((const uint2*)(gwf + (((k * 2 + ks) * 4 + nt) << 6)));
                mma_f16(acc[0][nt], a00_, a01_, a02_, a03_, bb.x, bb.y);
                mma_f16(acc[1][nt], a10_, a11_, a12_, a13_, bb.x, bb.y);
            }
        }
        __syncwarp();
        odyv = ndy;
        odxv = ndx;
    }

    // Epilogue: stage D in smem, then coalesced STG.128.
    __syncthreads();
    float* sd = (float*)smem;
    {
        const int pixb = wid * 32 + (lane >> 2);
        #pragma unroll
        for (int s = 0; s < 2; s++) {
            #pragma unroll
            for (int nt = 0; nt < 4; nt++) {
                const int row = nt * 8 + 2 * (lane & 3);
                const int px = pixb + s * 16;
                sd[row * DPAD + px]           = acc[s][nt][0];
                sd[(row + 1) * DPAD + px]     = acc[s][nt][1];
                sd[row * DPAD + px + 8]       = acc[s][nt][2];
                sd[(row + 1) * DPAD + px + 8] = acc[s][nt][3];
            }
        }
    }
    __syncthreads();
    #pragma unroll
    for (int i = 0; i < 8; i++) {
        const int j = tid + 256 * i;
        const int row = j >> 6;            // cout
        const int q = j & 63;              // float4 index within 256 pixels
        const float4 v = *(const float4*)(sd + row * DPAD + q * 4);
        *(float4*)(out + ((size_t)(b * Cc + row) * Tt + t) * HWsz + pix0 + q * 4) = v;
    }
}

extern "C" void kernel_launch(void* const* d_in, const int* in_sizes, int n_in,
                              void* d_out, int out_size) {
    const float* feat   = (const float*)d_in[0];
    const float* offset = (const float*)d_in[1];
    const float* weight = (const float*)d_in[2];
    float* out = (float*)d_out;

    cudaFuncSetAttribute(dcn_main, cudaFuncAttributeMaxDynamicSharedMemorySize, SM_TOTAL);

    prep_k<<<dim3(1153, 16), 256>>>(feat, weight);
    dcn_main<<<dim3(HWsz / 256, 16), 256, SM_TOTAL>>>(offset, out);
}

// round 9
// speedup vs baseline: 1.3146x; 1.3146x over previous
#include <cuda_runtime.h>
#include <cuda_fp16.h>
#include <cstdint>

#define Hh 192
#define Ww 192
#define HWsz (192*192)
#define Cc 32
#define Tt 8
#define KK 9

// Channels-last fp16 scratch: [B][T][HW][C]  (37.7 MB)
__device__ __half g_scratch_h[(size_t)2 * Tt * HWsz * Cc];
// tf32 weights in m16n8k8 fragment order: [t][tap][ks(4)][nt(4)][lane(32)][2]
__device__ uint32_t g_wfrag[(size_t)Tt * KK * 4 * 4 * 32 * 2];

__device__ __forceinline__ uint32_t f2tf32(float v) {
    uint32_t u;
    asm("cvt.rna.tf32.f32 %0, %1;" : "=r"(u) : "f"(v));
    return u;
}

__device__ __forceinline__ void mma_tf32(float* c, uint32_t a0, uint32_t a1,
                                         uint32_t a2, uint32_t a3,
                                         uint32_t b0, uint32_t b1) {
    asm volatile(
        "mma.sync.aligned.m16n8k8.row.col.f32.tf32.tf32.f32 "
        "{%0,%1,%2,%3}, {%4,%5,%6,%7}, {%8,%9}, {%0,%1,%2,%3};"
        : "+f"(c[0]), "+f"(c[1]), "+f"(c[2]), "+f"(c[3])
        : "r"(a0), "r"(a1), "r"(a2), "r"(a3), "r"(b0), "r"(b1));
}

// ---------- Kernel 1: transpose (+ tf32 weight prep in extra blocks) ----------
// grid = (1153, 16): x<1152 -> transpose tile; x==1152 -> wprep (t=by>>1, half=by&1)
__global__ __launch_bounds__(256) void prep_k(const float* __restrict__ feat,
                                              const float* __restrict__ weight) {
    if (blockIdx.x == 1152) {
        const int t = blockIdx.y >> 1;
        const int half = blockIdx.y & 1;
        for (int it = half * 18; it < half * 18 + 18; it++) {
            const int j = it * 256 + threadIdx.x;        // j < 9216
            const int reg   = j & 1;
            const int lane  = (j >> 1) & 31;
            const int ntile = (j >> 6) & 3;
            const int kstep = (j >> 8) & 3;
            const int tap   = j >> 10;
            const int cin  = kstep * 8 + (lane & 3) + reg * 4;
            const int cout = ntile * 8 + (lane >> 2);
            const float v = weight[((size_t)(t * Cc + cout) * Cc + cin) * KK + tap];
            g_wfrag[(size_t)t * 9216 + j] = f2tf32(v);
        }
        return;
    }
    __shared__ float tl[32][33];
    const int bt = blockIdx.y;
    const int b = bt >> 3, t = bt & 7;
    const int hw0 = blockIdx.x * 32;
    const int x = threadIdx.x & 31;
    const int y = threadIdx.x >> 5;
    #pragma unroll
    for (int j = 0; j < 4; j++) {
        const int c = y + j * 8;
        tl[c][x] = feat[((size_t)(b * Cc + c) * Tt + t) * HWsz + hw0 + x];
    }
    __syncthreads();
    uint32_t* gdst = (uint32_t*)g_scratch_h + ((size_t)bt * HWsz + hw0) * 16;
    #pragma unroll
    for (int it = 0; it < 2; it++) {
        const int idx = it * 256 + threadIdx.x;   // 0..511
        const int hwl = idx >> 4;
        const int cp  = idx & 15;
        const __half2 h = __floats2half2_rn(tl[2 * cp][hwl], tl[2 * cp + 1][hwl]);
        gdst[hwl * 16 + cp] = *(const uint32_t*)&h;
    }
}

// ---------- Kernel 2: fused deform-sample + mma.sync tf32 GEMM ----------
// smem: [A slabs 8w x 32 x 36 u32 = 36864B][params 8w x 32 x 12 u32 = 12288B]
// epilogue D (32 x 260 f32 = 33280B) reuses A region.
#define SM_PRM 36864
#define SM_TOTAL 49152
#define APAD 36
#define PPAD 12
#define DPAD 260

__global__ __launch_bounds__(256, 3) void dcn_main(
    const float* __restrict__ offset,   // [B, 18, T, H, W]
    float* __restrict__ out)            // [B, 32, T, H, W]
{
    extern __shared__ char smem[];
    const int tid  = threadIdx.x;
    const int wid  = tid >> 5;
    const int lane = tid & 31;
    const int bt = blockIdx.y;
    const int b = bt >> 3, t = bt & 7;
    const int pix0  = blockIdx.x * 256;
    const int pixw0 = pix0 + wid * 32;

    uint32_t* sa = (uint32_t*)smem + wid * (32 * APAD);              // A slab
    uint32_t* sp = (uint32_t*)(smem + SM_PRM) + wid * (32 * PPAD);   // params
    const uint2* sbase = (const uint2*)g_scratch_h + (size_t)bt * HWsz * 8 + (lane & 7);
    const float* offb = offset + ((size_t)b * 2 * KK * Tt + t) * HWsz + pixw0 + lane;
    const uint32_t* gwf = g_wfrag + (size_t)t * 9216 + lane * 2;

    // This lane's own pixel geometry (lane == pixel for phase A).
    const int mypix = pixw0 + lane;
    const int myh = (int)((unsigned)mypix / Ww);
    const int myw = mypix - myh * Ww;
    const size_t ostr = (size_t)Tt * HWsz;

    float acc[2][4][4];
    #pragma unroll
    for (int s = 0; s < 2; s++)
        #pragma unroll
        for (int n = 0; n < 4; n++)
            #pragma unroll
            for (int r = 0; r < 4; r++) acc[s][n][r] = 0.f;

    #pragma unroll 1
    for (int k = 0; k < KK; k++) {
        // ---- Phase A: per-lane bilinear params for this lane's pixel ----
        {
            const float dy = offb[(size_t)(2 * k) * ostr];
            const float dx = offb[(size_t)(2 * k + 1) * ostr];
            const int dky = k / 3 - 1;
            const int dkx = k - (k / 3) * 3 - 1;
            const float ys = dy + (float)(myh + dky);
            const float xs = dx + (float)(myw + dkx);

            const float y0f = floorf(ys), x0f = floorf(xs);
            const int iy0 = (int)y0f, ix0 = (int)x0f;
            const int iy1 = iy0 + 1,  ix1 = ix0 + 1;
            const float fy = ys - y0f, fx = xs - x0f;
            const float gy = 1.f - fy, gx = 1.f - fx;

            const bool vy0 = (unsigned)iy0 < Hh;
            const bool vy1 = (unsigned)iy1 < Hh;
            const bool vx0 = (unsigned)ix0 < Ww;
            const bool vx1 = (unsigned)ix1 < Ww;
            const int cy0 = min(max(iy0, 0), Hh - 1);
            const int cy1 = min(max(iy1, 0), Hh - 1);
            const int cx0 = min(max(ix0, 0), Ww - 1);
            const int cx1 = min(max(ix1, 0), Ww - 1);

            uint4 wq, iq;
            wq.x = __float_as_uint((vy0 && vx0) ? gy * gx : 0.f);
            wq.y = __float_as_uint((vy0 && vx1) ? gy * fx : 0.f);
            wq.z = __float_as_uint((vy1 && vx0) ? fy * gx : 0.f);
            wq.w = __float_as_uint((vy1 && vx1) ? fy * fx : 0.f);
            iq.x = (uint32_t)(cy0 * Ww + cx0);
            iq.y = (uint32_t)(cy0 * Ww + cx1);
            iq.z = (uint32_t)(cy1 * Ww + cx0);
            iq.w = (uint32_t)(cy1 * Ww + cx1);
            *(uint4*)(sp + lane * PPAD)     = wq;
            *(uint4*)(sp + lane * PPAD + 4) = iq;
        }
        __syncwarp();

        // ---- Phase B: gather + combine, 4 pixels per iteration ----
        #pragma unroll 2
        for (int p = 0; p < 8; p++) {
            const int pixl = p * 4 + (lane >> 3);

            const uint4 wq = *(const uint4*)(sp + pixl * PPAD);
            const uint4 iq = *(const uint4*)(sp + pixl * PPAD + 4);
            const float u00 = __uint_as_float(wq.x);
            const float u01 = __uint_as_float(wq.y);
            const float u10 = __uint_as_float(wq.z);
            const float u11 = __uint_as_float(wq.w);

            const uint2 q00 = sbase[(size_t)iq.x * 8];
            const uint2 q01 = sbase[(size_t)iq.y * 8];
            const uint2 q10 = sbase[(size_t)iq.z * 8];
            const uint2 q11 = sbase[(size_t)iq.w * 8];

            const float2 a00l = __half22float2(*(const __half2*)&q00.x);
            const float2 a00h = __half22float2(*(const __half2*)&q00.y);
            const float2 a01l = __half22float2(*(const __half2*)&q01.x);
            const float2 a01h = __half22float2(*(const __half2*)&q01.y);
            const float2 a10l = __half22float2(*(const __half2*)&q10.x);
            const float2 a10h = __half22float2(*(const __half2*)&q10.y);
            const float2 a11l = __half22float2(*(const __half2*)&q11.x);
            const float2 a11h = __half22float2(*(const __half2*)&q11.y);

            const float v0 = fmaf(u00, a00l.x, fmaf(u01, a01l.x, fmaf(u10, a10l.x, u11 * a11l.x)));
            const float v1 = fmaf(u00, a00l.y, fmaf(u01, a01l.y, fmaf(u10, a10l.y, u11 * a11l.y)));
            const float v2 = fmaf(u00, a00h.x, fmaf(u01, a01h.x, fmaf(u10, a10h.x, u11 * a11h.x)));
            const float v3 = fmaf(u00, a00h.y, fmaf(u01, a01h.y, fmaf(u10, a10h.y, u11 * a11h.y)));

            uint4 u; u.x = f2tf32(v0); u.y = f2tf32(v1); u.z = f2tf32(v2); u.w = f2tf32(v3);
            *(uint4*)(sa + pixl * APAD + (lane & 7) * 4) = u;
        }
        __syncwarp();

        // ---- MMA: D[32x32] += A[32x32] * W_k^T; B frags streamed from L1 ----
        const int r0 = lane >> 2;
        const int c0 = lane & 3;
        #pragma unroll
        for (int ks = 0; ks < 4; ks++) {
            const int cb = ks * 8 + c0;
            const uint32_t a00_ = sa[r0 * APAD + cb];
            const uint32_t a01_ = sa[(r0 + 8) * APAD + cb];
            const uint32_t a02_ = sa[r0 * APAD + cb + 4];
            const uint32_t a03_ = sa[(r0 + 8) * APAD + cb + 4];
            const uint32_t a10_ = sa[(r0 + 16) * APAD + cb];
            const uint32_t a11_ = sa[(r0 + 24) * APAD + cb];
            const uint32_t a12_ = sa[(r0 + 16) * APAD + cb + 4];
            const uint32_t a13_ = sa[(r0 + 24) * APAD + cb + 4];
            #pragma unroll
            for (int nt = 0; nt < 4; nt++) {
                const uint2 bb = __ldg((const uint2*)(gwf + (((k * 4 + ks) * 4 + nt) << 6)));
                mma_tf32(acc[0][nt], a00_, a01_, a02_, a03_, bb.x, bb.y);
                mma_tf32(acc[1][nt], a10_, a11_, a12_, a13_, bb.x, bb.y);
            }
        }
        __syncwarp();
    }

    // Epilogue: stage D in smem (reusing A region), then coalesced STG.128.
    __syncthreads();
    float* sd = (float*)smem;
    {
        const int pixb = wid * 32 + (lane >> 2);
        #pragma unroll
        for (int s = 0; s < 2; s++) {
            #pragma unroll
            for (int nt = 0; nt < 4; nt++) {
                const int row = nt * 8 + 2 * (lane & 3);
                const int px = pixb + s * 16;
                sd[row * DPAD + px]           = acc[s][nt][0];
                sd[(row + 1) * DPAD + px]     = acc[s][nt][1];
                sd[row * DPAD + px + 8]       = acc[s][nt][2];
                sd[(row + 1) * DPAD + px + 8] = acc[s][nt][3];
            }
        }
    }
    __syncthreads();
    #pragma unroll
    for (int i = 0; i < 8; i++) {
        const int j = tid + 256 * i;
        const int row = j >> 6;            // cout
        const int q = j & 63;              // float4 index within 256 pixels
        const float4 v = *(const float4*)(sd + row * DPAD + q * 4);
        *(float4*)(out + ((size_t)(b * Cc + row) * Tt + t) * HWsz + pix0 + q * 4) = v;
    }
}

extern "C" void kernel_launch(void* const* d_in, const int* in_sizes, int n_in,
                              void* d_out, int out_size) {
    const float* feat   = (const float*)d_in[0];
    const float* offset = (const float*)d_in[1];
    const float* weight = (const float*)d_in[2];
    float* out = (float*)d_out;

    cudaFuncSetAttribute(dcn_main, cudaFuncAttributeMaxDynamicSharedMemorySize, SM_TOTAL);

    prep_k<<<dim3(1153, 16), 256>>>(feat, weight);
    dcn_main<<<dim3(HWsz / 256, 16), 256, SM_TOTAL>>>(offset, out);
}

// round 10
// speedup vs baseline: 1.4672x; 1.1161x over previous
#include <cuda_runtime.h>
#include <cuda_fp16.h>
#include <cstdint>

#define Hh 192
#define Ww 192
#define HWsz (192*192)
#define Cc 32
#define Tt 8
#define KK 9

// Channels-last fp16 scratch: [B][T][HW][C]  (37.7 MB)
__device__ __half g_scratch_h[(size_t)2 * Tt * HWsz * Cc];
// fp16 weights in m16n8k16 fragment order: [t][tap][ks(2)][nt(4)][lane(32)][2]
__device__ uint32_t g_wfrag[(size_t)Tt * KK * 2 * 4 * 32 * 2];

__device__ __forceinline__ void mma_f16(float* c, uint32_t a0, uint32_t a1,
                                        uint32_t a2, uint32_t a3,
                                        uint32_t b0, uint32_t b1) {
    asm volatile(
        "mma.sync.aligned.m16n8k16.row.col.f32.f16.f16.f32 "
        "{%0,%1,%2,%3}, {%4,%5,%6,%7}, {%8,%9}, {%0,%1,%2,%3};"
        : "+f"(c[0]), "+f"(c[1]), "+f"(c[2]), "+f"(c[3])
        : "r"(a0), "r"(a1), "r"(a2), "r"(a3), "r"(b0), "r"(b1));
}

// ---------- Kernel 1: transpose (+ fp16 weight prep in extra blocks) ----------
// grid = (1153, 16): x<1152 -> transpose tile; x==1152 -> wprep (t=by>>1, half=by&1)
__global__ __launch_bounds__(256) void prep_k(const float* __restrict__ feat,
                                              const float* __restrict__ weight) {
    if (blockIdx.x == 1152) {
        const int t = blockIdx.y >> 1;
        const int half = blockIdx.y & 1;
        for (int it = half * 9; it < half * 9 + 9; it++) {
            const int j = it * 256 + threadIdx.x;    // j < 4608
            const int reg  = j & 1;
            const int lane = (j >> 1) & 31;
            const int nt   = (j >> 6) & 3;
            const int ks   = (j >> 8) & 1;
            const int tap  = j >> 9;                 // 0..8
            const int r0 = lane >> 2, c0 = lane & 3;
            const int cout = nt * 8 + r0;
            const int cin0 = ks * 16 + 2 * c0 + reg * 8;
            const float w0 = weight[((size_t)(t * Cc + cout) * Cc + cin0) * KK + tap];
            const float w1 = weight[((size_t)(t * Cc + cout) * Cc + cin0 + 1) * KK + tap];
            const __half2 h = __floats2half2_rn(w0, w1);
            g_wfrag[(size_t)t * 4608 + j] = *(const uint32_t*)&h;
        }
        return;
    }
    __shared__ float tl[32][33];
    const int bt = blockIdx.y;
    const int b = bt >> 3, t = bt & 7;
    const int hw0 = blockIdx.x * 32;
    const int x = threadIdx.x & 31;
    const int y = threadIdx.x >> 5;
    #pragma unroll
    for (int j = 0; j < 4; j++) {
        const int c = y + j * 8;
        tl[c][x] = feat[((size_t)(b * Cc + c) * Tt + t) * HWsz + hw0 + x];
    }
    __syncthreads();
    uint32_t* gdst = (uint32_t*)g_scratch_h + ((size_t)bt * HWsz + hw0) * 16;
    #pragma unroll
    for (int it = 0; it < 2; it++) {
        const int idx = it * 256 + threadIdx.x;   // 0..511
        const int hwl = idx >> 4;
        const int cp  = idx & 15;
        const __half2 h = __floats2half2_rn(tl[2 * cp][hwl], tl[2 * cp + 1][hwl]);
        gdst[hwl * 16 + cp] = *(const uint32_t*)&h;
    }
}

// ---------- Kernel 2: fused deform-sample + mma.sync fp16 GEMM ----------
// smem: [A slabs 8w x 32pix x 20 u32 = 20480B][params 8w x 32 x 12 u32 = 12288B]
// epilogue D (32 x 260 f32 = 33280B) reuses the whole region.
#define SM_PRM 20480
#define SM_TOTAL 33280
#define APAD2 20
#define PPAD 12
#define DPAD 260

__global__ __launch_bounds__(256, 3) void dcn_main(
    const float* __restrict__ offset,   // [B, 18, T, H, W]
    float* __restrict__ out)            // [B, 32, T, H, W]
{
    extern __shared__ char smem[];
    const int tid  = threadIdx.x;
    const int wid  = tid >> 5;
    const int lane = tid & 31;
    const int bt = blockIdx.y;
    const int b = bt >> 3, t = bt & 7;
    const int pix0  = blockIdx.x * 256;
    const int pixw0 = pix0 + wid * 32;

    uint32_t* sa = (uint32_t*)smem + wid * (32 * APAD2);             // fp16 A slab
    uint32_t* sp = (uint32_t*)(smem + SM_PRM) + wid * (32 * PPAD);   // params
    const uint2* sbase = (const uint2*)g_scratch_h + (size_t)bt * HWsz * 8 + (lane & 7);
    const float* offb = offset + ((size_t)b * 2 * KK * Tt + t) * HWsz + pixw0 + lane;
    const uint32_t* gwf = g_wfrag + (size_t)t * 4608 + lane * 2;

    // This lane's own pixel geometry (lane == pixel for phase A).
    const int mypix = pixw0 + lane;
    const int myh = (int)((unsigned)mypix / Ww);
    const int myw = mypix - myh * Ww;
    const size_t ostr = (size_t)Tt * HWsz;

    float acc[2][4][4];
    #pragma unroll
    for (int s = 0; s < 2; s++)
        #pragma unroll
        for (int n = 0; n < 4; n++)
            #pragma unroll
            for (int r = 0; r < 4; r++) acc[s][n][r] = 0.f;

    #pragma unroll 1
    for (int k = 0; k < KK; k++) {
        // ---- Phase A: per-lane bilinear params for this lane's pixel ----
        {
            const float dy = offb[(size_t)(2 * k) * ostr];
            const float dx = offb[(size_t)(2 * k + 1) * ostr];
            const int dky = k / 3 - 1;
            const int dkx = k - (k / 3) * 3 - 1;
            const float ys = dy + (float)(myh + dky);
            const float xs = dx + (float)(myw + dkx);

            const float y0f = floorf(ys), x0f = floorf(xs);
            const int iy0 = (int)y0f, ix0 = (int)x0f;
            const int iy1 = iy0 + 1,  ix1 = ix0 + 1;
            const float fy = ys - y0f, fx = xs - x0f;
            const float gy = 1.f - fy, gx = 1.f - fx;

            const bool vy0 = (unsigned)iy0 < Hh;
            const bool vy1 = (unsigned)iy1 < Hh;
            const bool vx0 = (unsigned)ix0 < Ww;
            const bool vx1 = (unsigned)ix1 < Ww;
            const int cy0 = min(max(iy0, 0), Hh - 1);
            const int cy1 = min(max(iy1, 0), Hh - 1);
            const int cx0 = min(max(ix0, 0), Ww - 1);
            const int cx1 = min(max(ix1, 0), Ww - 1);

            uint4 wq, iq;
            wq.x = __float_as_uint((vy0 && vx0) ? gy * gx : 0.f);
            wq.y = __float_as_uint((vy0 && vx1) ? gy * fx : 0.f);
            wq.z = __float_as_uint((vy1 && vx0) ? fy * gx : 0.f);
            wq.w = __float_as_uint((vy1 && vx1) ? fy * fx : 0.f);
            iq.x = (uint32_t)(cy0 * Ww + cx0);
            iq.y = (uint32_t)(cy0 * Ww + cx1);
            iq.z = (uint32_t)(cy1 * Ww + cx0);
            iq.w = (uint32_t)(cy1 * Ww + cx1);
            *(uint4*)(sp + lane * PPAD)     = wq;
            *(uint4*)(sp + lane * PPAD + 4) = iq;
        }
        __syncwarp();

        // ---- Phase B: gather + combine, 4 pixels per iteration ----
        #pragma unroll 2
        for (int p = 0; p < 8; p++) {
            const int pixl = p * 4 + (lane >> 3);

            const uint4 wq = *(const uint4*)(sp + pixl * PPAD);
            const uint4 iq = *(const uint4*)(sp + pixl * PPAD + 4);
            const float u00 = __uint_as_float(wq.x);
            const float u01 = __uint_as_float(wq.y);
            const float u10 = __uint_as_float(wq.z);
            const float u11 = __uint_as_float(wq.w);

            const uint2 q00 = sbase[(size_t)iq.x * 8];
            const uint2 q01 = sbase[(size_t)iq.y * 8];
            const uint2 q10 = sbase[(size_t)iq.z * 8];
            const uint2 q11 = sbase[(size_t)iq.w * 8];

            const float2 a00l = __half22float2(*(const __half2*)&q00.x);
            const float2 a00h = __half22float2(*(const __half2*)&q00.y);
            const float2 a01l = __half22float2(*(const __half2*)&q01.x);
            const float2 a01h = __half22float2(*(const __half2*)&q01.y);
            const float2 a10l = __half22float2(*(const __half2*)&q10.x);
            const float2 a10h = __half22float2(*(const __half2*)&q10.y);
            const float2 a11l = __half22float2(*(const __half2*)&q11.x);
            const float2 a11h = __half22float2(*(const __half2*)&q11.y);

            const float v0 = fmaf(u00, a00l.x, fmaf(u01, a01l.x, fmaf(u10, a10l.x, u11 * a11l.x)));
            const float v1 = fmaf(u00, a00l.y, fmaf(u01, a01l.y, fmaf(u10, a10l.y, u11 * a11l.y)));
            const float v2 = fmaf(u00, a00h.x, fmaf(u01, a01h.x, fmaf(u10, a10h.x, u11 * a11h.x)));
            const float v3 = fmaf(u00, a00h.y, fmaf(u01, a01h.y, fmaf(u10, a10h.y, u11 * a11h.y)));

            const __half2 h01 = __floats2half2_rn(v0, v1);
            const __half2 h23 = __floats2half2_rn(v2, v3);
            uint2 u; u.x = *(const uint32_t*)&h01; u.y = *(const uint32_t*)&h23;
            *(uint2*)(sa + pixl * APAD2 + (lane & 7) * 2) = u;
        }
        __syncwarp();

        // ---- MMA: D[32pix x 32cout] += A(fp16) * W_k^T(fp16), 2 K-steps of 16 ----
        const int g = lane >> 2;
        const int tq = lane & 3;
        #pragma unroll
        for (int ks = 0; ks < 2; ks++) {
            const int cb = tq + ks * 8;
            const uint32_t a00_ = sa[g * APAD2 + cb];
            const uint32_t a01_ = sa[(g + 8) * APAD2 + cb];
            const uint32_t a02_ = sa[g * APAD2 + cb + 4];
            const uint32_t a03_ = sa[(g + 8) * APAD2 + cb + 4];
            const uint32_t a10_ = sa[(g + 16) * APAD2 + cb];
            const uint32_t a11_ = sa[(g + 24) * APAD2 + cb];
            const uint32_t a12_ = sa[(g + 16) * APAD2 + cb + 4];
            const uint32_t a13_ = sa[(g + 24) * APAD2 + cb + 4];
            #pragma unroll
            for (int nt = 0; nt < 4; nt++) {
                const uint2 bb = __ldg((const uint2*)(gwf + (((k * 2 + ks) * 4 + nt) << 6)));
                mma_f16(acc[0][nt], a00_, a01_, a02_, a03_, bb.x, bb.y);
                mma_f16(acc[1][nt], a10_, a11_, a12_, a13_, bb.x, bb.y);
            }
        }
        __syncwarp();
    }

    // Epilogue: stage D in smem (reusing full region), then coalesced STG.128.
    __syncthreads();
    float* sd = (float*)smem;
    {
        const int pixb = wid * 32 + (lane >> 2);
        #pragma unroll
        for (int s = 0; s < 2; s++) {
            #pragma unroll
            for (int nt = 0; nt < 4; nt++) {
                const int row = nt * 8 + 2 * (lane & 3);
                const int px = pixb + s * 16;
                sd[row * DPAD + px]           = acc[s][nt][0];
                sd[(row + 1) * DPAD + px]     = acc[s][nt][1];
                sd[row * DPAD + px + 8]       = acc[s][nt][2];
                sd[(row + 1) * DPAD + px + 8] = acc[s][nt][3];
            }
        }
    }
    __syncthreads();
    #pragma unroll
    for (int i = 0; i < 8; i++) {
        const int j = tid + 256 * i;
        const int row = j >> 6;            // cout
        const int q = j & 63;              // float4 index within 256 pixels
        const float4 v = *(const float4*)(sd + row * DPAD + q * 4);
        *(float4*)(out + ((size_t)(b * Cc + row) * Tt + t) * HWsz + pix0 + q * 4) = v;
    }
}

extern "C" void kernel_launch(void* const* d_in, const int* in_sizes, int n_in,
                              void* d_out, int out_size) {
    const float* feat   = (const float*)d_in[0];
    const float* offset = (const float*)d_in[1];
    const float* weight = (const float*)d_in[2];
    float* out = (float*)d_out;

    cudaFuncSetAttribute(dcn_main, cudaFuncAttributeMaxDynamicSharedMemorySize, SM_TOTAL);

    prep_k<<<dim3(1153, 16), 256>>>(feat, weight);
    dcn_main<<<dim3(HWsz / 256, 16), 256, SM_TOTAL>>>(offset, out);
}

// round 11
// speedup vs baseline: 1.5901x; 1.0838x over previous
#include <cuda_runtime.h>
#include <cuda_fp16.h>
#include <cstdint>

#define Hh 192
#define Ww 192
#define HWsz (192*192)
#define Cc 32
#define Tt 8
#define KK 9

// Channels-last fp16 scratch: [B][T][HW][C]  (37.7 MB)
__device__ __half g_scratch_h[(size_t)2 * Tt * HWsz * Cc];
// fp16 weights in m16n8k16 fragment order: [t][tap][ks(2)][nt(4)][lane(32)][2]
__device__ uint32_t g_wfrag[(size_t)Tt * KK * 2 * 4 * 32 * 2];

__device__ __forceinline__ void mma_f16(float* c, uint32_t a0, uint32_t a1,
                                        uint32_t a2, uint32_t a3,
                                        uint32_t b0, uint32_t b1) {
    asm volatile(
        "mma.sync.aligned.m16n8k16.row.col.f32.f16.f16.f32 "
        "{%0,%1,%2,%3}, {%4,%5,%6,%7}, {%8,%9}, {%0,%1,%2,%3};"
        : "+f"(c[0]), "+f"(c[1]), "+f"(c[2]), "+f"(c[3])
        : "r"(a0), "r"(a1), "r"(a2), "r"(a3), "r"(b0), "r"(b1));
}

// ---------- Kernel 1: transpose (+ fp16 weight prep in extra blocks) ----------
__global__ __launch_bounds__(256) void prep_k(const float* __restrict__ feat,
                                              const float* __restrict__ weight) {
    if (blockIdx.x == 1152) {
        const int t = blockIdx.y >> 1;
        const int half = blockIdx.y & 1;
        for (int it = half * 9; it < half * 9 + 9; it++) {
            const int j = it * 256 + threadIdx.x;    // j < 4608
            const int reg  = j & 1;
            const int lane = (j >> 1) & 31;
            const int nt   = (j >> 6) & 3;
            const int ks   = (j >> 8) & 1;
            const int tap  = j >> 9;                 // 0..8
            const int r0 = lane >> 2, c0 = lane & 3;
            const int cout = nt * 8 + r0;
            const int cin0 = ks * 16 + 2 * c0 + reg * 8;
            const float w0 = weight[((size_t)(t * Cc + cout) * Cc + cin0) * KK + tap];
            const float w1 = weight[((size_t)(t * Cc + cout) * Cc + cin0 + 1) * KK + tap];
            const __half2 h = __floats2half2_rn(w0, w1);
            g_wfrag[(size_t)t * 4608 + j] = *(const uint32_t*)&h;
        }
        return;
    }
    __shared__ float tl[32][33];
    const int bt = blockIdx.y;
    const int b = bt >> 3, t = bt & 7;
    const int hw0 = blockIdx.x * 32;
    const int x = threadIdx.x & 31;
    const int y = threadIdx.x >> 5;
    #pragma unroll
    for (int j = 0; j < 4; j++) {
        const int c = y + j * 8;
        tl[c][x] = feat[((size_t)(b * Cc + c) * Tt + t) * HWsz + hw0 + x];
    }
    __syncthreads();
    uint32_t* gdst = (uint32_t*)g_scratch_h + ((size_t)bt * HWsz + hw0) * 16;
    #pragma unroll
    for (int it = 0; it < 2; it++) {
        const int idx = it * 256 + threadIdx.x;   // 0..511
        const int hwl = idx >> 4;
        const int cp  = idx & 15;
        const __half2 h = __floats2half2_rn(tl[2 * cp][hwl], tl[2 * cp + 1][hwl]);
        gdst[hwl * 16 + cp] = *(const uint32_t*)&h;
    }
}

// ---------- Kernel 2: fused deform-sample + mma.sync fp16 GEMM ----------
// Per-warp tile: 16 pixels x 32 cout (one m16 slab). CTA = 8 warps = 128 pixels.
// smem: [A slabs 8w x 16pix x 20 u32 = 10240B][params 8w x 16 x 12 u32 = 6144B]
// epilogue D (32 x 132 f32 = 16896B) reuses the whole region.
#define SM_PRM 10240
#define SM_TOTAL 16896
#define APAD2 20
#define PPAD 12
#define DPAD 132

__global__ __launch_bounds__(256, 4) void dcn_main(
    const float* __restrict__ offset,   // [B, 18, T, H, W]
    float* __restrict__ out)            // [B, 32, T, H, W]
{
    extern __shared__ char smem[];
    const int tid  = threadIdx.x;
    const int wid  = tid >> 5;
    const int lane = tid & 31;
    const int bt = blockIdx.y;
    const int b = bt >> 3, t = bt & 7;
    const int pix0  = blockIdx.x * 128;
    const int pixw0 = pix0 + wid * 16;

    uint32_t* sa = (uint32_t*)smem + wid * (16 * APAD2);             // fp16 A slab
    uint32_t* sp = (uint32_t*)(smem + SM_PRM) + wid * (16 * PPAD);   // params
    const uint2* sbase = (const uint2*)g_scratch_h + (size_t)bt * HWsz * 8 + (lane & 7);
    const float* offb = offset + ((size_t)b * 2 * KK * Tt + t) * HWsz + pixw0 + (lane & 15);
    const uint32_t* gwf = g_wfrag + (size_t)t * 4608 + lane * 2;

    // Phase-A pixel for this lane (lanes 16-31 duplicate 0-15; only lane<16 stores).
    const int mypix = pixw0 + (lane & 15);
    const int myh = (int)((unsigned)mypix / Ww);
    const int myw = mypix - myh * Ww;
    const size_t ostr = (size_t)Tt * HWsz;

    float acc[4][4];
    #pragma unroll
    for (int n = 0; n < 4; n++)
        #pragma unroll
        for (int r = 0; r < 4; r++) acc[n][r] = 0.f;

    #pragma unroll 1
    for (int k = 0; k < KK; k++) {
        // ---- Phase A: per-lane bilinear params ----
        {
            const float dy = offb[(size_t)(2 * k) * ostr];
            const float dx = offb[(size_t)(2 * k + 1) * ostr];
            const int dky = k / 3 - 1;
            const int dkx = k - (k / 3) * 3 - 1;
            const float ys = dy + (float)(myh + dky);
            const float xs = dx + (float)(myw + dkx);

            const float y0f = floorf(ys), x0f = floorf(xs);
            const int iy0 = (int)y0f, ix0 = (int)x0f;
            const int iy1 = iy0 + 1,  ix1 = ix0 + 1;
            const float fy = ys - y0f, fx = xs - x0f;
            const float gy = 1.f - fy, gx = 1.f - fx;

            const bool vy0 = (unsigned)iy0 < Hh;
            const bool vy1 = (unsigned)iy1 < Hh;
            const bool vx0 = (unsigned)ix0 < Ww;
            const bool vx1 = (unsigned)ix1 < Ww;
            const int cy0 = min(max(iy0, 0), Hh - 1);
            const int cy1 = min(max(iy1, 0), Hh - 1);
            const int cx0 = min(max(ix0, 0), Ww - 1);
            const int cx1 = min(max(ix1, 0), Ww - 1);

            uint4 wq, iq;
            wq.x = __float_as_uint((vy0 && vx0) ? gy * gx : 0.f);
            wq.y = __float_as_uint((vy0 && vx1) ? gy * fx : 0.f);
            wq.z = __float_as_uint((vy1 && vx0) ? fy * gx : 0.f);
            wq.w = __float_as_uint((vy1 && vx1) ? fy * fx : 0.f);
            iq.x = (uint32_t)(cy0 * Ww + cx0);
            iq.y = (uint32_t)(cy0 * Ww + cx1);
            iq.z = (uint32_t)(cy1 * Ww + cx0);
            iq.w = (uint32_t)(cy1 * Ww + cx1);
            if (lane < 16) {
                *(uint4*)(sp + lane * PPAD)     = wq;
                *(uint4*)(sp + lane * PPAD + 4) = iq;
            }
        }
        __syncwarp();

        // ---- Phase B: gather + combine, 4 pixels per iteration, 16 pixels ----
        #pragma unroll 2
        for (int p = 0; p < 4; p++) {
            const int pixl = p * 4 + (lane >> 3);

            const uint4 wq = *(const uint4*)(sp + pixl * PPAD);
            const uint4 iq = *(const uint4*)(sp + pixl * PPAD + 4);
            const float u00 = __uint_as_float(wq.x);
            const float u01 = __uint_as_float(wq.y);
            const float u10 = __uint_as_float(wq.z);
            const float u11 = __uint_as_float(wq.w);

            const uint2 q00 = sbase[(size_t)iq.x * 8];
            const uint2 q01 = sbase[(size_t)iq.y * 8];
            const uint2 q10 = sbase[(size_t)iq.z * 8];
            const uint2 q11 = sbase[(size_t)iq.w * 8];

            const float2 a00l = __half22float2(*(const __half2*)&q00.x);
            const float2 a00h = __half22float2(*(const __half2*)&q00.y);
            const float2 a01l = __half22float2(*(const __half2*)&q01.x);
            const float2 a01h = __half22float2(*(const __half2*)&q01.y);
            const float2 a10l = __half22float2(*(const __half2*)&q10.x);
            const float2 a10h = __half22float2(*(const __half2*)&q10.y);
            const float2 a11l = __half22float2(*(const __half2*)&q11.x);
            const float2 a11h = __half22float2(*(const __half2*)&q11.y);

            const float v0 = fmaf(u00, a00l.x, fmaf(u01, a01l.x, fmaf(u10, a10l.x, u11 * a11l.x)));
            const float v1 = fmaf(u00, a00l.y, fmaf(u01, a01l.y, fmaf(u10, a10l.y, u11 * a11l.y)));
            const float v2 = fmaf(u00, a00h.x, fmaf(u01, a01h.x, fmaf(u10, a10h.x, u11 * a11h.x)));
            const float v3 = fmaf(u00, a00h.y, fmaf(u01, a01h.y, fmaf(u10, a10h.y, u11 * a11h.y)));

            const __half2 h01 = __floats2half2_rn(v0, v1);
            const __half2 h23 = __floats2half2_rn(v2, v3);
            uint2 u; u.x = *(const uint32_t*)&h01; u.y = *(const uint32_t*)&h23;
            *(uint2*)(sa + pixl * APAD2 + (lane & 7) * 2) = u;
        }
        __syncwarp();

        // ---- MMA: D[16pix x 32cout] += A(fp16) * W_k^T(fp16), 2 K-steps of 16 ----
        const int g = lane >> 2;
        const int tq = lane & 3;
        #pragma unroll
        for (int ks = 0; ks < 2; ks++) {
            const int cb = tq + ks * 8;
            const uint32_t a0_ = sa[g * APAD2 + cb];
            const uint32_t a1_ = sa[(g + 8) * APAD2 + cb];
            const uint32_t a2_ = sa[g * APAD2 + cb + 4];
            const uint32_t a3_ = sa[(g + 8) * APAD2 + cb + 4];
            #pragma unroll
            for (int nt = 0; nt < 4; nt++) {
                const uint2 bb = __ldg((const uint2*)(gwf + (((k * 2 + ks) * 4 + nt) << 6)));
                mma_f16(acc[nt], a0_, a1_, a2_, a3_, bb.x, bb.y);
            }
        }
        __syncwarp();
    }

    // Epilogue: stage D[cout][pix] in smem (reusing full region), coalesced STG.128.
    __syncthreads();
    float* sd = (float*)smem;
    {
        const int g = lane >> 2;
        const int tq = lane & 3;
        const int pixb = wid * 16 + g;
        #pragma unroll
        for (int nt = 0; nt < 4; nt++) {
            const int row = nt * 8 + 2 * tq;
            sd[row * DPAD + pixb]           = acc[nt][0];
            sd[(row + 1) * DPAD + pixb]     = acc[nt][1];
            sd[row * DPAD + pixb + 8]       = acc[nt][2];
            sd[(row + 1) * DPAD + pixb + 8] = acc[nt][3];
        }
    }
    __syncthreads();
    #pragma unroll
    for (int i = 0; i < 4; i++) {
        const int j = tid + 256 * i;       // j < 1024
        const int row = j >> 5;            // cout
        const int q = j & 31;              // float4 index within 128 pixels
        const float4 v = *(const float4*)(sd + row * DPAD + q * 4);
        *(float4*)(out + ((size_t)(b * Cc + row) * Tt + t) * HWsz + pix0 + q * 4) = v;
    }
}

extern "C" void kernel_launch(void* const* d_in, const int* in_sizes, int n_in,
                              void* d_out, int out_size) {
    const float* feat   = (const float*)d_in[0];
    const float* offset = (const float*)d_in[1];
    const float* weight = (const float*)d_in[2];
    float* out = (float*)d_out;

    cudaFuncSetAttribute(dcn_main, cudaFuncAttributeMaxDynamicSharedMemorySize, SM_TOTAL);

    prep_k<<<dim3(1153, 16), 256>>>(feat, weight);
    dcn_main<<<dim3(HWsz / 128, 16), 256, SM_TOTAL>>>(offset, out);
}

// round 12
// speedup vs baseline: 1.6590x; 1.0434x over previous
#include <cuda_runtime.h>
#include <cuda_fp16.h>
#include <cstdint>

#define Hh 192
#define Ww 192
#define HWsz (192*192)
#define Cc 32
#define Tt 8
#define KK 9

// Channels-last fp16 scratch: [B][T][HW][C]  (37.7 MB)
__device__ __half g_scratch_h[(size_t)2 * Tt * HWsz * Cc];
// fp16 weights in m16n8k16 fragment order: [t][tap][ks(2)][nt(4)][lane(32)][2]
__device__ uint32_t g_wfrag[(size_t)Tt * KK * 2 * 4 * 32 * 2];

__device__ __forceinline__ void mma_f16(float* c, uint32_t a0, uint32_t a1,
                                        uint32_t a2, uint32_t a3,
                                        uint32_t b0, uint32_t b1) {
    asm volatile(
        "mma.sync.aligned.m16n8k16.row.col.f32.f16.f16.f32 "
        "{%0,%1,%2,%3}, {%4,%5,%6,%7}, {%8,%9}, {%0,%1,%2,%3};"
        : "+f"(c[0]), "+f"(c[1]), "+f"(c[2]), "+f"(c[3])
        : "r"(a0), "r"(a1), "r"(a2), "r"(a3), "r"(b0), "r"(b1));
}

// ---------- Kernel 1: transpose 128hw x 32c tiles (+ weight prep at x==288) ----------
#define TSTRIDE 133
__global__ __launch_bounds__(256) void prep_k(const float* __restrict__ feat,
                                              const float* __restrict__ weight) {
    if (blockIdx.x == 288) {
        const int t = blockIdx.y >> 1;
        const int half = blockIdx.y & 1;
        for (int it = half * 9; it < half * 9 + 9; it++) {
            const int j = it * 256 + threadIdx.x;    // j < 4608
            const int reg  = j & 1;
            const int lane = (j >> 1) & 31;
            const int nt   = (j >> 6) & 3;
            const int ks   = (j >> 8) & 1;
            const int tap  = j >> 9;                 // 0..8
            const int r0 = lane >> 2, c0 = lane & 3;
            const int cout = nt * 8 + r0;
            const int cin0 = ks * 16 + 2 * c0 + reg * 8;
            const float w0 = weight[((size_t)(t * Cc + cout) * Cc + cin0) * KK + tap];
            const float w1 = weight[((size_t)(t * Cc + cout) * Cc + cin0 + 1) * KK + tap];
            const __half2 h = __floats2half2_rn(w0, w1);
            g_wfrag[(size_t)t * 4608 + j] = *(const uint32_t*)&h;
        }
        return;
    }
    __shared__ float tl[32 * TSTRIDE];
    const int tid = threadIdx.x;
    const int bt = blockIdx.y;
    const int b = bt >> 3, t = bt & 7;
    const int hw0 = blockIdx.x * 128;

    // Read: 32 channel-rows x 128 floats; thread (c = tid>>3, f4 = tid&7) reads
    // 4 float4 at hw = 4*(f4 + 8*j). Lanes 0-7 cover one contiguous 128B line.
    const int c  = tid >> 3;
    const int f4 = tid & 7;
    const float* fsrc = feat + ((size_t)(b * Cc + c) * Tt + t) * HWsz + hw0;
    #pragma unroll
    for (int j = 0; j < 4; j++) {
        const float4 v = *(const float4*)(fsrc + (f4 + 8 * j) * 4);
        const int col = (f4 + 8 * j) * 4;
        tl[c * TSTRIDE + col]     = v.x;
        tl[c * TSTRIDE + col + 1] = v.y;
        tl[c * TSTRIDE + col + 2] = v.z;
        tl[c * TSTRIDE + col + 3] = v.w;
    }
    __syncthreads();

    // Write: 128 hw x 32 ch (fp16) = 128 x 4 uint4; thread handles 2 uint4.
    uint32_t* gdst = (uint32_t*)g_scratch_h + ((size_t)bt * HWsz + hw0) * 16;
    #pragma unroll
    for (int jj = 0; jj < 2; jj++) {
        const int u4 = tid + 256 * jj;   // 0..511
        const int hw = u4 >> 2;
        const int cp4 = u4 & 3;          // channel-octet
        uint4 o;
        uint32_t* op = &o.x;
        #pragma unroll
        for (int q = 0; q < 4; q++) {
            const int ch = cp4 * 8 + 2 * q;
            const __half2 h = __floats2half2_rn(tl[ch * TSTRIDE + hw],
                                                tl[(ch + 1) * TSTRIDE + hw]);
            op[q] = *(const uint32_t*)&h;
        }
        *(uint4*)(gdst + hw * 16 + cp4 * 4) = o;
    }
}

// ---------- Kernel 2: fused deform-sample + mma.sync fp16 GEMM ----------
// Per-warp tile: 16 pixels x 32 cout. CTA = 8 warps = 128 pixels. 5 CTAs/SM.
#define SM_PRM 10240
#define SM_TOTAL 16896
#define APAD2 20
#define PPAD 12
#define DPAD 132

__global__ __launch_bounds__(256, 5) void dcn_main(
    const float* __restrict__ offset,   // [B, 18, T, H, W]
    float* __restrict__ out)            // [B, 32, T, H, W]
{
    extern __shared__ char smem[];
    const int tid  = threadIdx.x;
    const int wid  = tid >> 5;
    const int lane = tid & 31;
    const int bt = blockIdx.y;
    const int b = bt >> 3, t = bt & 7;
    const int pix0  = blockIdx.x * 128;
    const int pixw0 = pix0 + wid * 16;

    uint32_t* sa = (uint32_t*)smem + wid * (16 * APAD2);             // fp16 A slab
    uint32_t* sp = (uint32_t*)(smem + SM_PRM) + wid * (16 * PPAD);   // params
    const uint2* sbase = (const uint2*)g_scratch_h + (size_t)bt * HWsz * 8 + (lane & 7);
    const float* offb = offset + ((size_t)b * 2 * KK * Tt + t) * HWsz + pixw0 + (lane & 15);
    const uint32_t* gwf = g_wfrag + (size_t)t * 4608 + lane * 2;

    const int mypix = pixw0 + (lane & 15);
    const int myh = (int)((unsigned)mypix / Ww);
    const int myw = mypix - myh * Ww;
    const size_t ostr = (size_t)Tt * HWsz;

    float acc[4][4];
    #pragma unroll
    for (int n = 0; n < 4; n++)
        #pragma unroll
        for (int r = 0; r < 4; r++) acc[n][r] = 0.f;

    #pragma unroll 1
    for (int k = 0; k < KK; k++) {
        // ---- Phase A: per-lane bilinear params ----
        {
            const float dy = offb[(size_t)(2 * k) * ostr];
            const float dx = offb[(size_t)(2 * k + 1) * ostr];
            const int dky = k / 3 - 1;
            const int dkx = k - (k / 3) * 3 - 1;
            const float ys = dy + (float)(myh + dky);
            const float xs = dx + (float)(myw + dkx);

            const float y0f = floorf(ys), x0f = floorf(xs);
            const int iy0 = (int)y0f, ix0 = (int)x0f;
            const int iy1 = iy0 + 1,  ix1 = ix0 + 1;
            const float fy = ys - y0f, fx = xs - x0f;
            const float gy = 1.f - fy, gx = 1.f - fx;

            const bool vy0 = (unsigned)iy0 < Hh;
            const bool vy1 = (unsigned)iy1 < Hh;
            const bool vx0 = (unsigned)ix0 < Ww;
            const bool vx1 = (unsigned)ix1 < Ww;
            const int cy0 = min(max(iy0, 0), Hh - 1);
            const int cy1 = min(max(iy1, 0), Hh - 1);
            const int cx0 = min(max(ix0, 0), Ww - 1);
            const int cx1 = min(max(ix1, 0), Ww - 1);

            uint4 wq, iq;
            wq.x = __float_as_uint((vy0 && vx0) ? gy * gx : 0.f);
            wq.y = __float_as_uint((vy0 && vx1) ? gy * fx : 0.f);
            wq.z = __float_as_uint((vy1 && vx0) ? fy * gx : 0.f);
            wq.w = __float_as_uint((vy1 && vx1) ? fy * fx : 0.f);
            iq.x = (uint32_t)(cy0 * Ww + cx0);
            iq.y = (uint32_t)(cy0 * Ww + cx1);
            iq.z = (uint32_t)(cy1 * Ww + cx0);
            iq.w = (uint32_t)(cy1 * Ww + cx1);
            if (lane < 16) {
                *(uint4*)(sp + lane * PPAD)     = wq;
                *(uint4*)(sp + lane * PPAD + 4) = iq;
            }
        }
        __syncwarp();

        // ---- Phase B: gather + combine, 4 pixels per iteration ----
        #pragma unroll 2
        for (int p = 0; p < 4; p++) {
            const int pixl = p * 4 + (lane >> 3);

            const uint4 wq = *(const uint4*)(sp + pixl * PPAD);
            const uint4 iq = *(const uint4*)(sp + pixl * PPAD + 4);
            const float u00 = __uint_as_float(wq.x);
            const float u01 = __uint_as_float(wq.y);
            const float u10 = __uint_as_float(wq.z);
            const float u11 = __uint_as_float(wq.w);

            const uint2 q00 = sbase[(size_t)iq.x * 8];
            const uint2 q01 = sbase[(size_t)iq.y * 8];
            const uint2 q10 = sbase[(size_t)iq.z * 8];
            const uint2 q11 = sbase[(size_t)iq.w * 8];

            const float2 a00l = __half22float2(*(const __half2*)&q00.x);
            const float2 a00h = __half22float2(*(const __half2*)&q00.y);
            const float2 a01l = __half22float2(*(const __half2*)&q01.x);
            const float2 a01h = __half22float2(*(const __half2*)&q01.y);
            const float2 a10l = __half22float2(*(const __half2*)&q10.x);
            const float2 a10h = __half22float2(*(const __half2*)&q10.y);
            const float2 a11l = __half22float2(*(const __half2*)&q11.x);
            const float2 a11h = __half22float2(*(const __half2*)&q11.y);

            const float v0 = fmaf(u00, a00l.x, fmaf(u01, a01l.x, fmaf(u10, a10l.x, u11 * a11l.x)));
            const float v1 = fmaf(u00, a00l.y, fmaf(u01, a01l.y, fmaf(u10, a10l.y, u11 * a11l.y)));
            const float v2 = fmaf(u00, a00h.x, fmaf(u01, a01h.x, fmaf(u10, a10h.x, u11 * a11h.x)));
            const float v3 = fmaf(u00, a00h.y, fmaf(u01, a01h.y, fmaf(u10, a10h.y, u11 * a11h.y)));

            const __half2 h01 = __floats2half2_rn(v0, v1);
            const __half2 h23 = __floats2half2_rn(v2, v3);
            uint2 u; u.x = *(const uint32_t*)&h01; u.y = *(const uint32_t*)&h23;
            *(uint2*)(sa + pixl * APAD2 + (lane & 7) * 2) = u;
        }
        __syncwarp();

        // ---- MMA: D[16pix x 32cout] += A(fp16) * W_k^T(fp16) ----
        const int g = lane >> 2;
        const int tq = lane & 3;
        #pragma unroll
        for (int ks = 0; ks < 2; ks++) {
            const int cb = tq + ks * 8;
            const uint32_t a0_ = sa[g * APAD2 + cb];
            const uint32_t a1_ = sa[(g + 8) * APAD2 + cb];
            const uint32_t a2_ = sa[g * APAD2 + cb + 4];
            const uint32_t a3_ = sa[(g + 8) * APAD2 + cb + 4];
            #pragma unroll
            for (int nt = 0; nt < 4; nt++) {
                const uint2 bb = __ldg((const uint2*)(gwf + (((k * 2 + ks) * 4 + nt) << 6)));
                mma_f16(acc[nt], a0_, a1_, a2_, a3_, bb.x, bb.y);
            }
        }
        __syncwarp();
    }

    // Epilogue: stage D[cout][pix] in smem, coalesced STG.128.
    __syncthreads();
    float* sd = (float*)smem;
    {
        const int g = lane >> 2;
        const int tq = lane & 3;
        const int pixb = wid * 16 + g;
        #pragma unroll
        for (int nt = 0; nt < 4; nt++) {
            const int row = nt * 8 + 2 * tq;
            sd[row * DPAD + pixb]           = acc[nt][0];
            sd[(row + 1) * DPAD + pixb]     = acc[nt][1];
            sd[row * DPAD + pixb + 8]       = acc[nt][2];
            sd[(row + 1) * DPAD + pixb + 8] = acc[nt][3];
        }
    }
    __syncthreads();
    #pragma unroll
    for (int i = 0; i < 4; i++) {
        const int j = tid + 256 * i;       // j < 1024
        const int row = j >> 5;            // cout
        const int q = j & 31;              // float4 index within 128 pixels
        const float4 v = *(const float4*)(sd + row * DPAD + q * 4);
        *(float4*)(out + ((size_t)(b * Cc + row) * Tt + t) * HWsz + pix0 + q * 4) = v;
    }
}

extern "C" void kernel_launch(void* const* d_in, const int* in_sizes, int n_in,
                              void* d_out, int out_size) {
    const float* feat   = (const float*)d_in[0];
    const float* offset = (const float*)d_in[1];
    const float* weight = (const float*)d_in[2];
    float* out = (float*)d_out;

    cudaFuncSetAttribute(dcn_main, cudaFuncAttributeMaxDynamicSharedMemorySize, SM_TOTAL);

    prep_k<<<dim3(289, 16), 256>>>(feat, weight);
    dcn_main<<<dim3(HWsz / 128, 16), 256, SM_TOTAL>>>(offset, out);
}

// round 13
// speedup vs baseline: 1.8398x; 1.1089x over previous
#include <cuda_runtime.h>
#include <cuda_fp16.h>
#include <cstdint>

#define Hh 192
#define Ww 192
#define HWsz (192*192)
#define Cc 32
#define Tt 8
#define KK 9

// Channels-last fp16 scratch: [B][T][HW][C]  (37.7 MB)
__device__ __half g_scratch_h[(size_t)2 * Tt * HWsz * Cc];
// fp16 weights in m16n8k16 fragment order: [t][tap][ks(2)][nt(4)][lane(32)][2]
__device__ uint32_t g_wfrag[(size_t)Tt * KK * 2 * 4 * 32 * 2];

__device__ __forceinline__ void mma_f16(float* c, uint32_t a0, uint32_t a1,
                                        uint32_t a2, uint32_t a3,
                                        uint32_t b0, uint32_t b1) {
    asm volatile(
        "mma.sync.aligned.m16n8k16.row.col.f32.f16.f16.f32 "
        "{%0,%1,%2,%3}, {%4,%5,%6,%7}, {%8,%9}, {%0,%1,%2,%3};"
        : "+f"(c[0]), "+f"(c[1]), "+f"(c[2]), "+f"(c[3])
        : "r"(a0), "r"(a1), "r"(a2), "r"(a3), "r"(b0), "r"(b1));
}

// ---------- Kernel 1: transpose 128hw x 32c tiles (+ weight prep at x==288) ----------
#define TSTRIDE 133
__global__ __launch_bounds__(256) void prep_k(const float* __restrict__ feat,
                                              const float* __restrict__ weight) {
    if (blockIdx.x == 288) {
        const int t = blockIdx.y >> 1;
        const int half = blockIdx.y & 1;
        for (int it = half * 9; it < half * 9 + 9; it++) {
            const int j = it * 256 + threadIdx.x;    // j < 4608
            const int reg  = j & 1;
            const int lane = (j >> 1) & 31;
            const int nt   = (j >> 6) & 3;
            const int ks   = (j >> 8) & 1;
            const int tap  = j >> 9;                 // 0..8
            const int r0 = lane >> 2, c0 = lane & 3;
            const int cout = nt * 8 + r0;
            const int cin0 = ks * 16 + 2 * c0 + reg * 8;
            const float w0 = weight[((size_t)(t * Cc + cout) * Cc + cin0) * KK + tap];
            const float w1 = weight[((size_t)(t * Cc + cout) * Cc + cin0 + 1) * KK + tap];
            const __half2 h = __floats2half2_rn(w0, w1);
            g_wfrag[(size_t)t * 4608 + j] = *(const uint32_t*)&h;
        }
        return;
    }
    __shared__ float tl[32 * TSTRIDE];
    const int tid = threadIdx.x;
    const int bt = blockIdx.y;
    const int b = bt >> 3, t = bt & 7;
    const int hw0 = blockIdx.x * 128;

    const int c  = tid >> 3;
    const int f4 = tid & 7;
    const float* fsrc = feat + ((size_t)(b * Cc + c) * Tt + t) * HWsz + hw0;
    #pragma unroll
    for (int j = 0; j < 4; j++) {
        const float4 v = *(const float4*)(fsrc + (f4 + 8 * j) * 4);
        const int col = (f4 + 8 * j) * 4;
        tl[c * TSTRIDE + col]     = v.x;
        tl[c * TSTRIDE + col + 1] = v.y;
        tl[c * TSTRIDE + col + 2] = v.z;
        tl[c * TSTRIDE + col + 3] = v.w;
    }
    __syncthreads();

    uint32_t* gdst = (uint32_t*)g_scratch_h + ((size_t)bt * HWsz + hw0) * 16;
    #pragma unroll
    for (int jj = 0; jj < 2; jj++) {
        const int u4 = tid + 256 * jj;   // 0..511
        const int hw = u4 >> 2;
        const int cp4 = u4 & 3;          // channel-octet
        uint4 o;
        uint32_t* op = &o.x;
        #pragma unroll
        for (int q = 0; q < 4; q++) {
            const int ch = cp4 * 8 + 2 * q;
            const __half2 h = __floats2half2_rn(tl[ch * TSTRIDE + hw],
                                                tl[(ch + 1) * TSTRIDE + hw]);
            op[q] = *(const uint32_t*)&h;
        }
        *(uint4*)(gdst + hw * 16 + cp4 * 4) = o;
    }
}

// ---------- Kernel 2: fused deform-sample + mma.sync fp16 GEMM ----------
// Per-warp tile: 16 pixels x 32 cout. CTA = 8 warps = 128 pixels.
#define SM_PRM 10240
#define SM_TOTAL 16896
#define APAD2 20      // A slab row pitch: 20 u32 = 80 B (64B data + 16B pad)
#define PPAD 12
#define DPAD 132

__global__ __launch_bounds__(256, 4) void dcn_main(
    const float* __restrict__ offset,   // [B, 18, T, H, W]
    float* __restrict__ out)            // [B, 32, T, H, W]
{
    extern __shared__ char smem[];
    const int tid  = threadIdx.x;
    const int wid  = tid >> 5;
    const int lane = tid & 31;
    const int bt = blockIdx.y;
    const int b = bt >> 3, t = bt & 7;
    const int pix0  = blockIdx.x * 128;
    const int pixw0 = pix0 + wid * 16;

    uint32_t* sa = (uint32_t*)smem + wid * (16 * APAD2);             // fp16 A slab
    uint32_t* sp = (uint32_t*)(smem + SM_PRM) + wid * (16 * PPAD);   // params
    const uint32_t sa_sh = (uint32_t)__cvta_generic_to_shared(sa);
    const float* offb = offset + ((size_t)b * 2 * KK * Tt + t) * HWsz + pixw0 + (lane & 15);
    const uint32_t* gwf = g_wfrag + (size_t)t * 4608 + lane * 2;
    // Gather base for this lane's channel-quad (16B of each 64B pixel row).
    const uint4* sb4 = (const uint4*)g_scratch_h + (size_t)bt * HWsz * 4 + (lane & 3);

    const int mypix = pixw0 + (lane & 15);
    const int myh = (int)((unsigned)mypix / Ww);
    const int myw = mypix - myh * Ww;
    const size_t ostr = (size_t)Tt * HWsz;

    float acc[4][4];
    #pragma unroll
    for (int n = 0; n < 4; n++)
        #pragma unroll
        for (int r = 0; r < 4; r++) acc[n][r] = 0.f;

    #pragma unroll 1
    for (int k = 0; k < KK; k++) {
        // ---- Phase A: per-lane bilinear params (lanes 0-15 own the 16 pixels) ----
        {
            const float dy = offb[(size_t)(2 * k) * ostr];
            const float dx = offb[(size_t)(2 * k + 1) * ostr];
            const int dky = k / 3 - 1;
            const int dkx = k - (k / 3) * 3 - 1;
            const float ys = dy + (float)(myh + dky);
            const float xs = dx + (float)(myw + dkx);

            const float y0f = floorf(ys), x0f = floorf(xs);
            const int iy0 = (int)y0f, ix0 = (int)x0f;
            const int iy1 = iy0 + 1,  ix1 = ix0 + 1;
            const float fy = ys - y0f, fx = xs - x0f;
            const float gy = 1.f - fy, gx = 1.f - fx;

            const bool vy0 = (unsigned)iy0 < Hh;
            const bool vy1 = (unsigned)iy1 < Hh;
            const bool vx0 = (unsigned)ix0 < Ww;
            const bool vx1 = (unsigned)ix1 < Ww;
            const int cy0 = min(max(iy0, 0), Hh - 1);
            const int cy1 = min(max(iy1, 0), Hh - 1);
            const int cx0 = min(max(ix0, 0), Ww - 1);
            const int cx1 = min(max(ix1, 0), Ww - 1);

            uint4 wq, iq;
            wq.x = __float_as_uint((vy0 && vx0) ? gy * gx : 0.f);
            wq.y = __float_as_uint((vy0 && vx1) ? gy * fx : 0.f);
            wq.z = __float_as_uint((vy1 && vx0) ? fy * gx : 0.f);
            wq.w = __float_as_uint((vy1 && vx1) ? fy * fx : 0.f);
            iq.x = (uint32_t)(cy0 * Ww + cx0);
            iq.y = (uint32_t)(cy0 * Ww + cx1);
            iq.z = (uint32_t)(cy1 * Ww + cx0);
            iq.w = (uint32_t)(cy1 * Ww + cx1);
            if (lane < 16) {
                *(uint4*)(sp + lane * PPAD)     = wq;
                *(uint4*)(sp + lane * PPAD + 4) = iq;
            }
        }
        __syncwarp();

        // ---- Phase B: 8 pixels/iter; lane = (pixel, ch-quad), LDG.128 gathers ----
        #pragma unroll
        for (int iter = 0; iter < 2; iter++) {
            const int pixl = iter * 8 + (lane >> 2);

            const uint4 wq = *(const uint4*)(sp + pixl * PPAD);
            const uint4 iq = *(const uint4*)(sp + pixl * PPAD + 4);

            float vs[8];
            {
                const uint4 qa = sb4[(size_t)iq.x * 4];
                const uint4 qb = sb4[(size_t)iq.y * 4];
                const float u00 = __uint_as_float(wq.x);
                const float u01 = __uint_as_float(wq.y);
                #pragma unroll
                for (int j = 0; j < 4; j++) {
                    const float2 fa = __half22float2(((const __half2*)&qa)[j]);
                    const float2 fb = __half22float2(((const __half2*)&qb)[j]);
                    vs[2 * j]     = fmaf(u00, fa.x, u01 * fb.x);
                    vs[2 * j + 1] = fmaf(u00, fa.y, u01 * fb.y);
                }
            }
            {
                const uint4 qc = sb4[(size_t)iq.z * 4];
                const uint4 qd = sb4[(size_t)iq.w * 4];
                const float u10 = __uint_as_float(wq.z);
                const float u11 = __uint_as_float(wq.w);
                #pragma unroll
                for (int j = 0; j < 4; j++) {
                    const float2 fc = __half22float2(((const __half2*)&qc)[j]);
                    const float2 fd = __half22float2(((const __half2*)&qd)[j]);
                    vs[2 * j]     = fmaf(u10, fc.x, fmaf(u11, fd.x, vs[2 * j]));
                    vs[2 * j + 1] = fmaf(u10, fc.y, fmaf(u11, fd.y, vs[2 * j + 1]));
                }
            }
            uint4 o;
            ((__half2*)&o)[0] = __floats2half2_rn(vs[0], vs[1]);
            ((__half2*)&o)[1] = __floats2half2_rn(vs[2], vs[3]);
            ((__half2*)&o)[2] = __floats2half2_rn(vs[4], vs[5]);
            ((__half2*)&o)[3] = __floats2half2_rn(vs[6], vs[7]);
            *(uint4*)(sa + pixl * APAD2 + (lane & 3) * 4) = o;
        }
        __syncwarp();

        // ---- MMA: A frags via ldmatrix.x4; D[16pix x 32cout] ----
        #pragma unroll
        for (int ks = 0; ks < 2; ks++) {
            uint32_t a0_, a1_, a2_, a3_;
            const uint32_t lmaddr = sa_sh + (lane & 15) * (APAD2 * 4)
                                          + (lane >> 4) * 16 + ks * 32;
            asm volatile(
                "ldmatrix.sync.aligned.m8n8.x4.shared.b16 {%0,%1,%2,%3}, [%4];"
                : "=r"(a0_), "=r"(a1_), "=r"(a2_), "=r"(a3_) : "r"(lmaddr));
            #pragma unroll
            for (int nt = 0; nt < 4; nt++) {
                const uint2 bb = __ldg((const uint2*)(gwf + (((k * 2 + ks) * 4 + nt) << 6)));
                mma_f16(acc[nt], a0_, a1_, a2_, a3_, bb.x, bb.y);
            }
        }
        __syncwarp();
    }

    // Epilogue: stage D[cout][pix] in smem, coalesced STG.128.
    __syncthreads();
    float* sd = (float*)smem;
    {
        const int g = lane >> 2;
        const int tq = lane & 3;
        const int pixb = wid * 16 + g;
        #pragma unroll
        for (int nt = 0; nt < 4; nt++) {
            const int row = nt * 8 + 2 * tq;
            sd[row * DPAD + pixb]           = acc[nt][0];
            sd[(row + 1) * DPAD + pixb]     = acc[nt][1];
            sd[row * DPAD + pixb + 8]       = acc[nt][2];
            sd[(row + 1) * DPAD + pixb + 8] = acc[nt][3];
        }
    }
    __syncthreads();
    #pragma unroll
    for (int i = 0; i < 4; i++) {
        const int j = tid + 256 * i;       // j < 1024
        const int row = j >> 5;            // cout
        const int q = j & 31;              // float4 index within 128 pixels
        const float4 v = *(const float4*)(sd + row * DPAD + q * 4);
        *(float4*)(out + ((size_t)(b * Cc + row) * Tt + t) * HWsz + pix0 + q * 4) = v;
    }
}

extern "C" void kernel_launch(void* const* d_in, const int* in_sizes, int n_in,
                              void* d_out, int out_size) {
    const float* feat   = (const float*)d_in[0];
    const float* offset = (const float*)d_in[1];
    const float* weight = (const float*)d_in[2];
    float* out = (float*)d_out;

    cudaFuncSetAttribute(dcn_main, cudaFuncAttributeMaxDynamicSharedMemorySize, SM_TOTAL);

    prep_k<<<dim3(289, 16), 256>>>(feat, weight);
    dcn_main<<<dim3(HWsz / 128, 16), 256, SM_TOTAL>>>(offset, out);
}